// round 13
// baseline (speedup 1.0000x reference)
#include <cuda_runtime.h>
#include <cuda_bf16.h>
#include <math.h>
#include <stdint.h>

#define B_ 2
#define L_ 2048
#define D_ 2048
#define H_ 16
#define DH 128
#define M_ 4096           // B*L
#define KTOT 2048

// ---------------- scratch (__device__ globals; no allocation) ----------------
__device__ __nv_bfloat16 g_qh[(size_t)B_*H_*L_*DH];   // post-rope hi/lo
__device__ __nv_bfloat16 g_ql[(size_t)B_*H_*L_*DH];
__device__ __nv_bfloat16 g_kh[(size_t)B_*H_*L_*DH];
__device__ __nv_bfloat16 g_kl[(size_t)B_*H_*L_*DH];
__device__ __nv_bfloat16 g_vh[(size_t)B_*H_*L_*DH];
__device__ __nv_bfloat16 g_vl[(size_t)B_*H_*L_*DH];
__device__ __nv_bfloat16 g_xhi[(size_t)M_*KTOT];      // x split; later ao split
__device__ __nv_bfloat16 g_xlo[(size_t)M_*KTOT];
__device__ __nv_bfloat16 g_whi[(size_t)D_*KTOT];      // transposed weights [N,K]
__device__ __nv_bfloat16 g_wlo[(size_t)D_*KTOT];
__device__ float g_ct[L_ * 64];                        // cos table [l][j]
__device__ float g_st[L_ * 64];                        // sin table [l][j]

// ---------------- helpers (baseline PTX only) ----------
__device__ __forceinline__ uint32_t smem_u32(const void* p) {
    uint32_t a;
    asm("{ .reg .u64 t; cvta.to.shared.u64 t, %1; cvt.u32.u64 %0, t; }" : "=r"(a) : "l"(p));
    return a;
}
#define SWZ128(off) ((off) ^ (((off) >> 3) & 0x70))

#define CPASYNC16(sa, ga) \
    asm volatile("cp.async.cg.shared.global [%0], [%1], 16;" :: "r"(sa), "l"(ga) : "memory")
#define CPCOMMIT() asm volatile("cp.async.commit_group;" ::: "memory")
#define CPWAIT(n)  asm volatile("cp.async.wait_group %0;" :: "n"(n) : "memory")

#define LDSM4(R, addr)                                                        \
    asm volatile("ldmatrix.sync.aligned.m8n8.x4.shared.b16 {%0,%1,%2,%3}, [%4];" \
        : "=r"((R)[0]), "=r"((R)[1]), "=r"((R)[2]), "=r"((R)[3]) : "r"(addr))
#define LDSM4T(R, addr)                                                       \
    asm volatile("ldmatrix.sync.aligned.m8n8.x4.trans.shared.b16 {%0,%1,%2,%3}, [%4];" \
        : "=r"((R)[0]), "=r"((R)[1]), "=r"((R)[2]), "=r"((R)[3]) : "r"(addr))

#define MMA16816(d, a, b0, b1)                                                \
    asm volatile("mma.sync.aligned.m16n8k16.row.col.f32.bf16.bf16.f32 "       \
        "{%0,%1,%2,%3}, {%4,%5,%6,%7}, {%8,%9}, {%0,%1,%2,%3};"               \
        : "+f"((d)[0]), "+f"((d)[1]), "+f"((d)[2]), "+f"((d)[3])              \
        : "r"((a)[0]), "r"((a)[1]), "r"((a)[2]), "r"((a)[3]), "r"(b0), "r"(b1))

__device__ __forceinline__ uint32_t pack_bf16x2(float lo, float hi) {
    uint32_t d;
    asm("cvt.rn.bf16x2.f32 %0, %1, %2;" : "=r"(d) : "f"(hi), "f"(lo));
    return d;
}
__device__ __forceinline__ __nv_bfloat162 split_hi(float a, float b,
                                                   __nv_bfloat162& lo) {
    __nv_bfloat16 h0 = __float2bfloat16(a);
    __nv_bfloat16 h1 = __float2bfloat16(b);
    lo = __nv_bfloat162{__float2bfloat16(a - __bfloat162float(h0)),
                        __float2bfloat16(b - __bfloat162float(h1))};
    return __nv_bfloat162{h0, h1};
}

// ---------------------------------------------------------------------------
// RoPE cos/sin table: 2048 x 64
// ---------------------------------------------------------------------------
__global__ void freq_table()
{
    int idx = blockIdx.x * 256 + threadIdx.x;   // 512 x 256 = 131072
    int l = idx >> 6, j = idx & 63;
    float invf = (float)exp2(-(double)(2 * j) * (18.931568569324174 / 128.0));
    float ang = (float)l * invf;
    float c, s;
    sincosf(ang, &s, &c);   // sincosf(x, sin*, cos*) — sin FIRST
    g_ct[idx] = c;
    g_st[idx] = s;
}

// ---------------------------------------------------------------------------
// fp32 -> bf16 hi/lo split (x only)
// ---------------------------------------------------------------------------
__global__ void conv_plain(const float* __restrict__ in,
                           __nv_bfloat16* __restrict__ hi,
                           __nv_bfloat16* __restrict__ lo, int n4)
{
    int i = blockIdx.x * blockDim.x + threadIdx.x;
    if (i >= n4) return;
    float4 v = ((const float4*)in)[i];
    __nv_bfloat162 l01, l23;
    __nv_bfloat162 h01 = split_hi(v.x, v.y, l01);
    __nv_bfloat162 h23 = split_hi(v.z, v.w, l23);
    __nv_bfloat162* hp = (__nv_bfloat162*)hi;
    __nv_bfloat162* lp = (__nv_bfloat162*)lo;
    hp[2*i]   = h01; hp[2*i+1] = h23;
    lp[2*i]   = l01; lp[2*i+1] = l23;
}

// ---------------------------------------------------------------------------
// W [K,N] fp32 -> Wt [N,K] bf16 hi/lo (32x32 smem tile transpose)
// ---------------------------------------------------------------------------
__global__ void conv_T(const float* __restrict__ W,
                       __nv_bfloat16* __restrict__ hi,
                       __nv_bfloat16* __restrict__ lo)
{
    __shared__ float tl[32][33];
    const int n0 = blockIdx.x * 32, k0 = blockIdx.y * 32;
    const int tx = threadIdx.x, ty = threadIdx.y;   // 32 x 8
#pragma unroll
    for (int i = 0; i < 4; i++)
        tl[ty + 8*i][tx] = W[(size_t)(k0 + ty + 8*i) * D_ + n0 + tx];
    __syncthreads();
#pragma unroll
    for (int i = 0; i < 4; i++) {
        float v = tl[tx][ty + 8*i];
        __nv_bfloat16 h = __float2bfloat16(v);
        __nv_bfloat16 l = __float2bfloat16(v - __bfloat162float(h));
        size_t o = (size_t)(n0 + ty + 8*i) * KTOT + k0 + tx;
        hi[o] = h;
        lo[o] = l;
    }
}

// ---------------------------------------------------------------------------
// HMMA bf16 split GEMM: C[M,N] = A[M,K] * Wt[N,K]^T  (3-term hi/lo)
// 128x128 CTA tile, 4 warps (2x2 grid, warp tile 64x64), KC=32,
// hi|lo interleaved per 128B row ([hi 64B | lo 64B]), SW128 swizzle,
// 2-stage cp.async, 2 CTAs/SM.
// mode 1: fp32 row-major [M,N]
// mode 2: bf16 hi/lo scatter to [B,H,L,Dh]
// mode 3: RoPE (table) + scale, bf16 hi/lo scatter to [B,H,L,Dh]
// ---------------------------------------------------------------------------
#define GTM 128
#define GTN 128
#define KC  32
#define NCH (KTOT / KC)
#define STAGEB 32768           // A 16KB (128 rows x [hi64|lo64]) + B 16KB
#define GSMEM (2 * STAGEB)

extern __shared__ char gsm[];

__global__ __launch_bounds__(128, 2)
void gemm_bf16(const __nv_bfloat16* __restrict__ Ahi, const __nv_bfloat16* __restrict__ Alo,
               const __nv_bfloat16* __restrict__ Bhi, const __nv_bfloat16* __restrict__ Blo,
               float* __restrict__ C,
               __nv_bfloat16* __restrict__ Ch, __nv_bfloat16* __restrict__ Cl,
               int mode, float scale)
{
    const uint32_t sb = smem_u32(gsm);
    const int t = threadIdx.x;
    const int lane = t & 31, wid = t >> 5;
    const int wm = wid & 1, wn = wid >> 1;        // 2 x 2 warp grid, 64x64 tiles
    const int row0 = blockIdx.y * GTM;
    const int col0 = blockIdx.x * GTN;

    float acc[4][8][4];
#pragma unroll
    for (int i = 0; i < 4; i++)
#pragma unroll
        for (int j = 0; j < 8; j++)
#pragma unroll
            for (int q = 0; q < 4; q++) acc[i][j][q] = 0.f;

    // per-thread load invariants: q = t&7 selects [hi k0-7 | hi k8-15 | hi k16-23 |
    // hi k24-31 | lo k0-7 | ... ] 16B unit within the 128B row
    const int lq = t & 7;
    const int lcolb = (lq & 3) * 8;
    const __nv_bfloat16* srcA = (lq & 4) ? Alo : Ahi;
    const __nv_bfloat16* srcB = (lq & 4) ? Blo : Bhi;

#define LOAD_STAGE(ch, s) do {                                                \
    _Pragma("unroll")                                                         \
    for (int i = 0; i < 16; i++) {                                            \
        int u = t + i * 128;                                                  \
        int reg = i >> 3;              /* 0 = A, 1 = B */                     \
        int rr = (u >> 3) & 127;                                              \
        uint32_t sw = sb + (s) * STAGEB + (reg << 14)                         \
                    + SWZ128((rr << 7) + (lq << 4));                          \
        size_t go = (size_t)((reg ? col0 : row0) + rr) * KTOT                 \
                  + (ch) * KC + lcolb;                                        \
        CPASYNC16(sw, (reg ? srcB : srcA) + go);                              \
    }                                                                         \
    CPCOMMIT();                                                               \
} while (0)

    LOAD_STAGE(0, 0);

    for (int ch = 0; ch < NCH; ch++) {
        if (ch + 1 < NCH) {
            LOAD_STAGE(ch + 1, (ch + 1) & 1);
            CPWAIT(1);
        } else {
            CPWAIT(0);
        }
        __syncthreads();

        const uint32_t base = sb + (ch & 1) * STAGEB;
#pragma unroll
        for (int kk = 0; kk < 2; kk++) {
            const int kbh = kk * 32;        // hi bytes within row
            const int kbl = 64 + kk * 32;   // lo bytes within row
            uint32_t ah[4][4], al[4][4], bh[4][4], bl[4][4];
#pragma unroll
            for (int mf = 0; mf < 4; mf++) {
                int m = wm * 64 + mf * 16 + ((lane >> 3) & 1) * 8 + (lane & 7);
                int ko = (lane >> 4) << 4;
                LDSM4(ah[mf], base + SWZ128((m << 7) + kbh + ko));
                LDSM4(al[mf], base + SWZ128((m << 7) + kbl + ko));
            }
#pragma unroll
            for (int ng = 0; ng < 4; ng++) {
                int n = wn * 64 + ng * 16 + ((lane >> 4) & 1) * 8 + (lane & 7);
                int ko = ((lane >> 3) & 1) << 4;
                LDSM4(bh[ng], base + 16384 + SWZ128((n << 7) + kbh + ko));
                LDSM4(bl[ng], base + 16384 + SWZ128((n << 7) + kbl + ko));
            }
            // term-major: 16 independent mmas between accumulator reuses
#pragma unroll
            for (int mf = 0; mf < 4; mf++)
#pragma unroll
                for (int ng = 0; ng < 4; ng++) {
                    MMA16816(acc[mf][2*ng],   ah[mf], bh[ng][0], bh[ng][1]);
                    MMA16816(acc[mf][2*ng+1], ah[mf], bh[ng][2], bh[ng][3]);
                }
#pragma unroll
            for (int mf = 0; mf < 4; mf++)
#pragma unroll
                for (int ng = 0; ng < 4; ng++) {
                    MMA16816(acc[mf][2*ng],   ah[mf], bl[ng][0], bl[ng][1]);
                    MMA16816(acc[mf][2*ng+1], ah[mf], bl[ng][2], bl[ng][3]);
                }
#pragma unroll
            for (int mf = 0; mf < 4; mf++)
#pragma unroll
                for (int ng = 0; ng < 4; ng++) {
                    MMA16816(acc[mf][2*ng],   al[mf], bh[ng][0], bh[ng][1]);
                    MMA16816(acc[mf][2*ng+1], al[mf], bh[ng][2], bh[ng][3]);
                }
        }
        __syncthreads();
    }

    // epilogue: warp covers rows wm*64..+63, cols wn*64..+63
#pragma unroll
    for (int mf = 0; mf < 4; mf++) {
        int mrow = row0 + wm * 64 + mf * 16 + (lane >> 2);
        if (mode == 1) {
            float* d0 = &C[(size_t)mrow * D_ + col0 + wn * 64];
            float* d1 = d0 + (size_t)8 * D_;
#pragma unroll
            for (int nf = 0; nf < 8; nf++) {
                int n = nf * 8 + (lane & 3) * 2;
                *(float2*)&d0[n] = make_float2(acc[mf][nf][0], acc[mf][nf][1]);
                *(float2*)&d1[n] = make_float2(acc[mf][nf][2], acc[mf][nf][3]);
            }
        } else {
            int b = mrow >> 11, l = mrow & (L_ - 1), h = col0 >> 7;
            size_t base0 = (((size_t)(b * H_ + h)) * L_ + l) * DH + wn * 64;
            size_t base1 = base0 + (size_t)8 * DH;
#pragma unroll
            for (int nf = 0; nf < 8; nf++) {
                int n = nf * 8 + (lane & 3) * 2;
                int j = (wn * 64 + n) >> 1;
#pragma unroll
                for (int half = 0; half < 2; half++) {
                    size_t bb = half ? base1 : base0;
                    float v0 = acc[mf][nf][half * 2], v1 = acc[mf][nf][half * 2 + 1];
                    if (mode == 3) {
                        int le = l + half * 8;
                        float c = __ldg(&g_ct[le * 64 + j]);
                        float s = __ldg(&g_st[le * 64 + j]);
                        float r0 = (v0 * c - v1 * s) * scale;
                        float r1 = (v1 * c + v0 * s) * scale;
                        v0 = r0; v1 = r1;
                    }
                    __nv_bfloat162 lo;
                    __nv_bfloat162 hi2 = split_hi(v0, v1, lo);
                    *(__nv_bfloat162*)&Ch[bb + n] = hi2;
                    *(__nv_bfloat162*)&Cl[bb + n] = lo;
                }
            }
        }
    }
}

// ---------------------------------------------------------------------------
// HMMA flash attention, causal. Br=128, Bc=64, 8 warps (16 rows each).
// S = 3-term bf16 split; P hi/lo split; PV = Ph*Vh + Pl*Vh + Ph*Vl.
// cp.async double buffer. Epilogue writes bf16 hi/lo split of output.
// ---------------------------------------------------------------------------
#define FBR 128
#define FBC 64
#define SQH 0
#define SQL 32768
#define SKV 65536                 // stages at 65536 + s*65536
#define FSMEMB (65536 + 2 * 65536)  // 192 KB

extern __shared__ char fsm8[];

__global__ __launch_bounds__(256, 1)
void flash_kernel()
{
    const uint32_t sb = smem_u32(fsm8);
    const int t = threadIdx.x, lane = t & 31, w = t >> 5;
    const int qt = (int)gridDim.x - 1 - (int)blockIdx.x;   // heavy tiles first
    const int bh = blockIdx.y;
    const int q0 = qt * FBR;
    const size_t hb = (size_t)bh * L_ * DH;

    // load Q hi/lo (once)
#pragma unroll
    for (int i = 0; i < 8; i++) {
        int u = t + i * 256;
        int c = u >> 10, r = (u >> 3) & 127, e8 = (u & 7) << 3;
        uint32_t so = c * 16384 + SWZ128((r << 7) + (e8 << 1));
        size_t go = hb + (size_t)(q0 + r) * DH + c * 64 + e8;
        *(uint4*)(fsm8 + SQH + so) = *(const uint4*)&g_qh[go];
        *(uint4*)(fsm8 + SQL + so) = *(const uint4*)&g_ql[go];
    }

#define LOADKV(j, s) do {                                                     \
    int kv0_ = (j) * FBC;                                                     \
    uint32_t stb = sb + SKV + (s) * 65536;                                    \
    _Pragma("unroll")                                                         \
    for (int i = 0; i < 4; i++) {                                             \
        int u = t + i * 256;                                                  \
        int c = u >> 9, r = (u >> 3) & 63, e8 = (u & 7) << 3;                 \
        uint32_t so = stb + c * 8192 + SWZ128((r << 7) + (e8 << 1));          \
        size_t go = hb + (size_t)(kv0_ + r) * DH + c * 64 + e8;               \
        CPASYNC16(so,         g_kh + go);                                     \
        CPASYNC16(so + 16384, g_kl + go);                                     \
        CPASYNC16(so + 32768, g_vh + go);                                     \
        CPASYNC16(so + 49152, g_vl + go);                                     \
    }                                                                         \
    CPCOMMIT();                                                               \
} while (0)

    const int jmax = qt * 2 + 1;
    LOADKV(0, 0);

    float o[16][4];
#pragma unroll
    for (int i = 0; i < 16; i++)
#pragma unroll
        for (int q = 0; q < 4; q++) o[i][q] = 0.f;
    float m0 = -INFINITY, m1 = -INFINITY, l0 = 0.f, l1 = 0.f;

    // per-lane invariant offsets
    const int mrow = w * 16 + ((lane >> 3) & 1) * 8 + (lane & 7);
    const int kAoff = (lane >> 4) << 4;
    const int nrow = ((lane >> 4) & 1) * 8 + (lane & 7);
    const int kBoff = ((lane >> 3) & 1) << 4;
    const int vrow = ((lane >> 3) & 1) * 8 + (lane & 7);
    const int vcol8 = ((lane >> 4) & 1) * 8;
    const int r0 = lane >> 2;          // warp-local row (also +8)
    const int cql = (lane & 3) * 2;    // col pair base within n8

    for (int j0 = 0; j0 <= jmax; j0++) {
        if (j0 < jmax) { LOADKV(j0 + 1, (j0 + 1) & 1); CPWAIT(1); }
        else CPWAIT(0);
        __syncthreads();

        const uint32_t kvb = sb + SKV + (j0 & 1) * 65536;
        const int kv0 = j0 * FBC;

        // ---- S = Q K^T (3-term) ----
        float s[8][4];
#pragma unroll
        for (int i = 0; i < 8; i++)
#pragma unroll
            for (int q = 0; q < 4; q++) s[i][q] = 0.f;

#pragma unroll
        for (int c = 0; c < 2; c++) {
#pragma unroll
            for (int kk = 0; kk < 4; kk++) {
                const int kb = kk * 32;
                uint32_t ah[4], al[4];
                uint32_t qa = sb + SQH + c * 16384 + SWZ128((mrow << 7) + kb + kAoff);
                LDSM4(ah, qa);
                LDSM4(al, qa + 32768);
#pragma unroll
                for (int ng = 0; ng < 4; ng++) {
                    uint32_t kh[4], kl[4];
                    uint32_t ka = kvb + c * 8192
                                + SWZ128(((ng * 16 + nrow) << 7) + kb + kBoff);
                    LDSM4(kh, ka);
                    LDSM4(kl, ka + 16384);
                    MMA16816(s[2*ng],   ah, kh[0], kh[1]);
                    MMA16816(s[2*ng+1], ah, kh[2], kh[3]);
                    MMA16816(s[2*ng],   ah, kl[0], kl[1]);
                    MMA16816(s[2*ng+1], ah, kl[2], kl[3]);
                    MMA16816(s[2*ng],   al, kh[0], kh[1]);
                    MMA16816(s[2*ng+1], al, kh[2], kh[3]);
                }
            }
        }

        // ---- causal mask ----
        const int qr0 = q0 + w * 16 + r0;
        if (kv0 + 63 > qr0) {
#pragma unroll
            for (int nf = 0; nf < 8; nf++) {
                int kc = kv0 + nf * 8 + cql;
                if (kc > qr0)     s[nf][0] = -INFINITY;
                if (kc + 1 > qr0) s[nf][1] = -INFINITY;
                if (kc > qr0 + 8)     s[nf][2] = -INFINITY;
                if (kc + 1 > qr0 + 8) s[nf][3] = -INFINITY;
            }
        }

        // ---- online softmax (rows warp-local; reduce over 4-lane row group) ----
        float mt0 = -INFINITY, mt1 = -INFINITY;
#pragma unroll
        for (int nf = 0; nf < 8; nf++) {
            mt0 = fmaxf(mt0, fmaxf(s[nf][0], s[nf][1]));
            mt1 = fmaxf(mt1, fmaxf(s[nf][2], s[nf][3]));
        }
        mt0 = fmaxf(mt0, __shfl_xor_sync(0xffffffffu, mt0, 1));
        mt0 = fmaxf(mt0, __shfl_xor_sync(0xffffffffu, mt0, 2));
        mt1 = fmaxf(mt1, __shfl_xor_sync(0xffffffffu, mt1, 1));
        mt1 = fmaxf(mt1, __shfl_xor_sync(0xffffffffu, mt1, 2));

        float nm0 = fmaxf(m0, mt0), nm1 = fmaxf(m1, mt1);
        float a0 = __expf(m0 - nm0), a1 = __expf(m1 - nm1);
        m0 = nm0; m1 = nm1;

        float rs0 = 0.f, rs1 = 0.f;
        uint32_t pah[4][4], pal[4][4];
#pragma unroll
        for (int kk = 0; kk < 4; kk++) {
#pragma unroll
            for (int half = 0; half < 2; half++) {
                int nf = 2 * kk + half;
                float p00 = __expf(s[nf][0] - m0);
                float p01 = __expf(s[nf][1] - m0);
                float p10 = __expf(s[nf][2] - m1);
                float p11 = __expf(s[nf][3] - m1);
                rs0 += p00 + p01;
                rs1 += p10 + p11;
                uint32_t ph0 = pack_bf16x2(p00, p01);
                uint32_t ph1 = pack_bf16x2(p10, p11);
                __nv_bfloat162 b0 = *(__nv_bfloat162*)&ph0;
                __nv_bfloat162 b1 = *(__nv_bfloat162*)&ph1;
                uint32_t pl0 = pack_bf16x2(p00 - __bfloat162float(b0.x),
                                           p01 - __bfloat162float(b0.y));
                uint32_t pl1 = pack_bf16x2(p10 - __bfloat162float(b1.x),
                                           p11 - __bfloat162float(b1.y));
                pah[kk][half * 2]     = ph0;
                pah[kk][half * 2 + 1] = ph1;
                pal[kk][half * 2]     = pl0;
                pal[kk][half * 2 + 1] = pl1;
            }
        }
        rs0 += __shfl_xor_sync(0xffffffffu, rs0, 1);
        rs0 += __shfl_xor_sync(0xffffffffu, rs0, 2);
        rs1 += __shfl_xor_sync(0xffffffffu, rs1, 1);
        rs1 += __shfl_xor_sync(0xffffffffu, rs1, 2);
        l0 = l0 * a0 + rs0;
        l1 = l1 * a1 + rs1;

#pragma unroll
        for (int nf = 0; nf < 16; nf++) {
            o[nf][0] *= a0; o[nf][1] *= a0;
            o[nf][2] *= a1; o[nf][3] *= a1;
        }

        // ---- O += Ph*(Vh+Vl) + Pl*Vh ----
#pragma unroll
        for (int kk = 0; kk < 4; kk++) {
#pragma unroll
            for (int dg = 0; dg < 8; dg++) {
                int dcol = dg * 16 + vcol8;
                int c = dcol >> 6, e = dcol & 63;
                uint32_t va = kvb + 32768 + c * 8192
                            + SWZ128(((kk * 16 + vrow) << 7) + (e << 1));
                uint32_t vh[4], vl[4];
                LDSM4T(vh, va);
                LDSM4T(vl, va + 16384);
                MMA16816(o[2*dg],   pah[kk], vh[0], vh[1]);
                MMA16816(o[2*dg+1], pah[kk], vh[2], vh[3]);
                MMA16816(o[2*dg],   pal[kk], vh[0], vh[1]);
                MMA16816(o[2*dg+1], pal[kk], vh[2], vh[3]);
                MMA16816(o[2*dg],   pah[kk], vl[0], vl[1]);
                MMA16816(o[2*dg+1], pah[kk], vl[2], vl[3]);
            }
        }
        __syncthreads();   // all warps done with this stage before it's refilled
    }

    // ---- epilogue: normalize, split to bf16 hi/lo, write [B,L,H*Dh] ----
    const int b = bh >> 4, h = bh & 15;
    const float inv0 = 1.f / l0, inv1 = 1.f / l1;
    const int qrow0 = q0 + w * 16 + r0;
    size_t o0b = ((size_t)b * L_ + qrow0) * D_ + h * DH;
    size_t o1b = o0b + (size_t)8 * D_;
#pragma unroll
    for (int nf = 0; nf < 16; nf++) {
        int col = nf * 8 + cql;
        __nv_bfloat162 lo0, lo1;
        __nv_bfloat162 hi0 = split_hi(o[nf][0] * inv0, o[nf][1] * inv0, lo0);
        __nv_bfloat162 hi1 = split_hi(o[nf][2] * inv1, o[nf][3] * inv1, lo1);
        *(__nv_bfloat162*)&g_xhi[o0b + col] = hi0;
        *(__nv_bfloat162*)&g_xlo[o0b + col] = lo0;
        *(__nv_bfloat162*)&g_xhi[o1b + col] = hi1;
        *(__nv_bfloat162*)&g_xlo[o1b + col] = lo1;
    }
}

// ---------------------------------------------------------------------------
extern "C" void kernel_launch(void* const* d_in, const int* in_sizes, int n_in,
                              void* d_out, int out_size)
{
    const float* x  = (const float*)d_in[0];
    const float* Wq = (const float*)d_in[1];
    const float* Wk = (const float*)d_in[2];
    const float* Wv = (const float*)d_in[3];
    const float* Wo = (const float*)d_in[4];
    float* out = (float*)d_out;

    __nv_bfloat16 *xh, *xl, *wh, *wl, *qh, *ql, *kh, *kl, *vh, *vl;
    cudaGetSymbolAddress((void**)&xh, g_xhi);
    cudaGetSymbolAddress((void**)&xl, g_xlo);
    cudaGetSymbolAddress((void**)&wh, g_whi);
    cudaGetSymbolAddress((void**)&wl, g_wlo);
    cudaGetSymbolAddress((void**)&qh, g_qh);
    cudaGetSymbolAddress((void**)&ql, g_ql);
    cudaGetSymbolAddress((void**)&kh, g_kh);
    cudaGetSymbolAddress((void**)&kl, g_kl);
    cudaGetSymbolAddress((void**)&vh, g_vh);
    cudaGetSymbolAddress((void**)&vl, g_vl);

    cudaFuncSetAttribute(flash_kernel,
                         cudaFuncAttributeMaxDynamicSharedMemorySize, FSMEMB);
    cudaFuncSetAttribute(gemm_bf16,
                         cudaFuncAttributeMaxDynamicSharedMemorySize, GSMEM);

    const int n4 = M_ * KTOT / 4;
    dim3 tgrid(D_ / 32, KTOT / 32), tblk(32, 8);
    dim3 ggrid(D_ / GTN, M_ / GTM);   // (16, 32)
    const float qscale = 0.08838834764831845f;  // 1/sqrt(128)

    freq_table<<<512, 256>>>();
    conv_plain<<<(n4 + 255) / 256, 256>>>(x, xh, xl, n4);

    conv_T<<<tgrid, tblk>>>(Wq, wh, wl);
    gemm_bf16<<<ggrid, 128, GSMEM>>>(xh, xl, wh, wl, nullptr, qh, ql, 3, qscale);
    conv_T<<<tgrid, tblk>>>(Wk, wh, wl);
    gemm_bf16<<<ggrid, 128, GSMEM>>>(xh, xl, wh, wl, nullptr, kh, kl, 3, 1.0f);
    conv_T<<<tgrid, tblk>>>(Wv, wh, wl);
    gemm_bf16<<<ggrid, 128, GSMEM>>>(xh, xl, wh, wl, nullptr, vh, vl, 2, 1.0f);

    flash_kernel<<<dim3(16, 32), 256, FSMEMB>>>();   // overwrites xh/xl with ao split

    conv_T<<<tgrid, tblk>>>(Wo, wh, wl);
    gemm_bf16<<<ggrid, 128, GSMEM>>>(xh, xl, wh, wl, out, nullptr, nullptr, 1, 1.0f);
}

// round 14
// speedup vs baseline: 1.0731x; 1.0731x over previous
#include <cuda_runtime.h>
#include <cuda_bf16.h>
#include <math.h>
#include <stdint.h>

#define B_ 2
#define L_ 2048
#define D_ 2048
#define H_ 16
#define DH 128
#define M_ 4096           // B*L
#define KTOT 2048
#define WSLAB ((size_t)D_ * KTOT)

// ---------------- scratch (__device__ globals; no allocation) ----------------
__device__ __nv_bfloat16 g_qh[(size_t)B_*H_*L_*DH];   // post-rope hi/lo
__device__ __nv_bfloat16 g_ql[(size_t)B_*H_*L_*DH];
__device__ __nv_bfloat16 g_kh[(size_t)B_*H_*L_*DH];
__device__ __nv_bfloat16 g_kl[(size_t)B_*H_*L_*DH];
__device__ __nv_bfloat16 g_vh[(size_t)B_*H_*L_*DH];
__device__ __nv_bfloat16 g_vl[(size_t)B_*H_*L_*DH];
__device__ __nv_bfloat16 g_xhi[(size_t)M_*KTOT];      // x split; later ao split
__device__ __nv_bfloat16 g_xlo[(size_t)M_*KTOT];
__device__ __nv_bfloat16 g_whi[4 * WSLAB];            // Wq|Wk|Wv|Wo transposed [N,K]
__device__ __nv_bfloat16 g_wlo[4 * WSLAB];
__device__ float g_ct[L_ * 64];                        // cos table [l][j]
__device__ float g_st[L_ * 64];                        // sin table [l][j]

// ---------------- helpers (baseline PTX only) ----------
__device__ __forceinline__ uint32_t smem_u32(const void* p) {
    uint32_t a;
    asm("{ .reg .u64 t; cvta.to.shared.u64 t, %1; cvt.u32.u64 %0, t; }" : "=r"(a) : "l"(p));
    return a;
}
#define SWZ128(off) ((off) ^ (((off) >> 3) & 0x70))

#define CPASYNC16(sa, ga) \
    asm volatile("cp.async.cg.shared.global [%0], [%1], 16;" :: "r"(sa), "l"(ga) : "memory")
#define CPCOMMIT() asm volatile("cp.async.commit_group;" ::: "memory")
#define CPWAIT(n)  asm volatile("cp.async.wait_group %0;" :: "n"(n) : "memory")

#define LDSM4(R, addr)                                                        \
    asm volatile("ldmatrix.sync.aligned.m8n8.x4.shared.b16 {%0,%1,%2,%3}, [%4];" \
        : "=r"((R)[0]), "=r"((R)[1]), "=r"((R)[2]), "=r"((R)[3]) : "r"(addr))
#define LDSM4T(R, addr)                                                       \
    asm volatile("ldmatrix.sync.aligned.m8n8.x4.trans.shared.b16 {%0,%1,%2,%3}, [%4];" \
        : "=r"((R)[0]), "=r"((R)[1]), "=r"((R)[2]), "=r"((R)[3]) : "r"(addr))

#define MMA16816(d, a, b0, b1)                                                \
    asm volatile("mma.sync.aligned.m16n8k16.row.col.f32.bf16.bf16.f32 "       \
        "{%0,%1,%2,%3}, {%4,%5,%6,%7}, {%8,%9}, {%0,%1,%2,%3};"               \
        : "+f"((d)[0]), "+f"((d)[1]), "+f"((d)[2]), "+f"((d)[3])              \
        : "r"((a)[0]), "r"((a)[1]), "r"((a)[2]), "r"((a)[3]), "r"(b0), "r"(b1))

__device__ __forceinline__ uint32_t pack_bf16x2(float lo, float hi) {
    uint32_t d;
    asm("cvt.rn.bf16x2.f32 %0, %1, %2;" : "=r"(d) : "f"(hi), "f"(lo));
    return d;
}
__device__ __forceinline__ __nv_bfloat162 split_hi(float a, float b,
                                                   __nv_bfloat162& lo) {
    __nv_bfloat16 h0 = __float2bfloat16(a);
    __nv_bfloat16 h1 = __float2bfloat16(b);
    lo = __nv_bfloat162{__float2bfloat16(a - __bfloat162float(h0)),
                        __float2bfloat16(b - __bfloat162float(h1))};
    return __nv_bfloat162{h0, h1};
}

// ---------------------------------------------------------------------------
// RoPE cos/sin table: 2048 x 64
// ---------------------------------------------------------------------------
__global__ void freq_table()
{
    int idx = blockIdx.x * 256 + threadIdx.x;   // 512 x 256 = 131072
    int l = idx >> 6, j = idx & 63;
    float invf = (float)exp2(-(double)(2 * j) * (18.931568569324174 / 128.0));
    float ang = (float)l * invf;
    float c, s;
    sincosf(ang, &s, &c);   // sincosf(x, sin*, cos*) — sin FIRST
    g_ct[idx] = c;
    g_st[idx] = s;
}

// ---------------------------------------------------------------------------
// fp32 -> bf16 hi/lo split (x only)
// ---------------------------------------------------------------------------
__global__ void conv_plain(const float* __restrict__ in,
                           __nv_bfloat16* __restrict__ hi,
                           __nv_bfloat16* __restrict__ lo, int n4)
{
    int i = blockIdx.x * blockDim.x + threadIdx.x;
    if (i >= n4) return;
    float4 v = ((const float4*)in)[i];
    __nv_bfloat162 l01, l23;
    __nv_bfloat162 h01 = split_hi(v.x, v.y, l01);
    __nv_bfloat162 h23 = split_hi(v.z, v.w, l23);
    __nv_bfloat162* hp = (__nv_bfloat162*)hi;
    __nv_bfloat162* lp = (__nv_bfloat162*)lo;
    hp[2*i]   = h01; hp[2*i+1] = h23;
    lp[2*i]   = l01; lp[2*i+1] = l23;
}

// ---------------------------------------------------------------------------
// All 4 weights [K,N] fp32 -> [N,K] bf16 hi/lo slabs (z = weight index)
// ---------------------------------------------------------------------------
__global__ void conv_T4(const float* __restrict__ W0, const float* __restrict__ W1,
                        const float* __restrict__ W2, const float* __restrict__ W3)
{
    __shared__ float tl[32][33];
    const int z = blockIdx.z;
    const float* W = (z == 0) ? W0 : (z == 1) ? W1 : (z == 2) ? W2 : W3;
    __nv_bfloat16* hi = g_whi + (size_t)z * WSLAB;
    __nv_bfloat16* lo = g_wlo + (size_t)z * WSLAB;
    const int n0 = blockIdx.x * 32, k0 = blockIdx.y * 32;
    const int tx = threadIdx.x, ty = threadIdx.y;   // 32 x 8
#pragma unroll
    for (int i = 0; i < 4; i++)
        tl[ty + 8*i][tx] = W[(size_t)(k0 + ty + 8*i) * D_ + n0 + tx];
    __syncthreads();
#pragma unroll
    for (int i = 0; i < 4; i++) {
        float v = tl[tx][ty + 8*i];
        __nv_bfloat16 h = __float2bfloat16(v);
        __nv_bfloat16 l = __float2bfloat16(v - __bfloat162float(h));
        size_t o = (size_t)(n0 + ty + 8*i) * KTOT + k0 + tx;
        hi[o] = h;
        lo[o] = l;
    }
}

// ---------------------------------------------------------------------------
// Shared GEMM mainloop (R12 config: 256 thr, 8 warps 2x4, warp tile 64x32,
// KC=64, separated hi/lo arrays, 2-stage cp.async)
// ---------------------------------------------------------------------------
#define GTM 128
#define GTN 128
#define KC  64
#define NCH (KTOT / KC)
#define STAGEB 65536           // Ahi|Alo|Bhi|Blo, 16KB each
#define GSMEM (2 * STAGEB)

extern __shared__ char gsm[];

__device__ __forceinline__ void gemm_mainloop(
    const __nv_bfloat16* __restrict__ Ahi, const __nv_bfloat16* __restrict__ Alo,
    const __nv_bfloat16* __restrict__ Bhi, const __nv_bfloat16* __restrict__ Blo,
    int row0, int col0, float acc[4][4][4])
{
    const uint32_t sb = smem_u32(gsm);
    const int t = threadIdx.x;
    const int lane = t & 31, wid = t >> 5;
    const int wm = wid & 1, wn = wid >> 1;

#define LOAD_STAGE(ch, s) do {                                                \
    _Pragma("unroll")                                                         \
    for (int i = 0; i < 4; i++) {                                             \
        int u = t + i * 256;                                                  \
        int rr = u >> 3;                                                      \
        int ce = (u & 7) << 3;                                                \
        uint32_t sw = sb + (s) * STAGEB + SWZ128((rr << 7) + (ce << 1));      \
        size_t goA = (size_t)(row0 + rr) * KTOT + (ch) * KC + ce;             \
        size_t goB = (size_t)(col0 + rr) * KTOT + (ch) * KC + ce;             \
        CPASYNC16(sw,         Ahi + goA);                                     \
        CPASYNC16(sw + 16384, Alo + goA);                                     \
        CPASYNC16(sw + 32768, Bhi + goB);                                     \
        CPASYNC16(sw + 49152, Blo + goB);                                     \
    }                                                                         \
    CPCOMMIT();                                                               \
} while (0)

    LOAD_STAGE(0, 0);

    for (int ch = 0; ch < NCH; ch++) {
        if (ch + 1 < NCH) {
            LOAD_STAGE(ch + 1, (ch + 1) & 1);
            CPWAIT(1);
        } else {
            CPWAIT(0);
        }
        __syncthreads();

        const uint32_t base = sb + (ch & 1) * STAGEB;
#pragma unroll
        for (int k16 = 0; k16 < 4; k16++) {
            const int kb = k16 * 32;
            uint32_t ah[4][4], al[4][4], bh2[2][4], bl2[2][4];
#pragma unroll
            for (int mf = 0; mf < 4; mf++) {
                int m = wm * 64 + mf * 16 + ((lane >> 3) & 1) * 8 + (lane & 7);
                uint32_t ad = base + SWZ128((m << 7) + kb + ((lane >> 4) << 4));
                LDSM4(ah[mf], ad);
                LDSM4(al[mf], ad + 16384);
            }
#pragma unroll
            for (int nf2 = 0; nf2 < 2; nf2++) {
                int n = wn * 32 + nf2 * 16 + ((lane >> 4) & 1) * 8 + (lane & 7);
                uint32_t bd = base + 32768 + SWZ128((n << 7) + kb + (((lane >> 3) & 1) << 4));
                LDSM4(bh2[nf2], bd);
                LDSM4(bl2[nf2], bd + 16384);
            }
#pragma unroll
            for (int mf = 0; mf < 4; mf++)
#pragma unroll
                for (int nf = 0; nf < 4; nf++)
                    MMA16816(acc[mf][nf], ah[mf], bh2[nf >> 1][(nf & 1) * 2],
                             bh2[nf >> 1][(nf & 1) * 2 + 1]);
#pragma unroll
            for (int mf = 0; mf < 4; mf++)
#pragma unroll
                for (int nf = 0; nf < 4; nf++)
                    MMA16816(acc[mf][nf], ah[mf], bl2[nf >> 1][(nf & 1) * 2],
                             bl2[nf >> 1][(nf & 1) * 2 + 1]);
#pragma unroll
            for (int mf = 0; mf < 4; mf++)
#pragma unroll
                for (int nf = 0; nf < 4; nf++)
                    MMA16816(acc[mf][nf], al[mf], bh2[nf >> 1][(nf & 1) * 2],
                             bh2[nf >> 1][(nf & 1) * 2 + 1]);
        }
        __syncthreads();
    }
#undef LOAD_STAGE
}

// ---------------------------------------------------------------------------
// Fused QKV GEMM: grid (48, 32). wsel = bx>>4 selects weight slab + output.
// wsel 0: q (rope + 1/sqrt(Dh)); wsel 1: k (rope); wsel 2: v (plain split).
// ---------------------------------------------------------------------------
__global__ __launch_bounds__(256, 1)
void gemm_qkv(const __nv_bfloat16* __restrict__ Ahi,
              const __nv_bfloat16* __restrict__ Alo)
{
    const int wsel = blockIdx.x >> 4;
    const int col0 = (blockIdx.x & 15) << 7;
    const int row0 = blockIdx.y * GTM;
    const __nv_bfloat16* Bhi = g_whi + (size_t)wsel * WSLAB;
    const __nv_bfloat16* Blo = g_wlo + (size_t)wsel * WSLAB;

    float acc[4][4][4];
#pragma unroll
    for (int i = 0; i < 4; i++)
#pragma unroll
        for (int j = 0; j < 4; j++)
#pragma unroll
            for (int q = 0; q < 4; q++) acc[i][j][q] = 0.f;

    gemm_mainloop(Ahi, Alo, Bhi, Blo, row0, col0, acc);

    __nv_bfloat16* Ch = (wsel == 0) ? g_qh : (wsel == 1) ? g_kh : g_vh;
    __nv_bfloat16* Cl = (wsel == 0) ? g_ql : (wsel == 1) ? g_kl : g_vl;
    const bool rope = (wsel < 2);
    const float scale = (wsel == 0) ? 0.08838834764831845f : 1.0f;

    const int lane = threadIdx.x & 31, wid = threadIdx.x >> 5;
    const int wm = wid & 1, wn = wid >> 1;
#pragma unroll
    for (int mf = 0; mf < 4; mf++) {
        int mrow = row0 + wm * 64 + mf * 16 + (lane >> 2);
        int b = mrow >> 11, l = mrow & (L_ - 1), h = col0 >> 7;
        size_t base0 = (((size_t)(b * H_ + h)) * L_ + l) * DH;
        size_t base1 = base0 + (size_t)8 * DH;
#pragma unroll
        for (int nf = 0; nf < 4; nf++) {
            int n = wn * 32 + nf * 8 + (lane & 3) * 2;
            int j = n >> 1;
#pragma unroll
            for (int half = 0; half < 2; half++) {
                size_t bb = half ? base1 : base0;
                float v0 = acc[mf][nf][half * 2], v1 = acc[mf][nf][half * 2 + 1];
                if (rope) {
                    int le = l + half * 8;
                    float c = __ldg(&g_ct[le * 64 + j]);
                    float s = __ldg(&g_st[le * 64 + j]);
                    float r0 = (v0 * c - v1 * s) * scale;
                    float r1 = (v1 * c + v0 * s) * scale;
                    v0 = r0; v1 = r1;
                }
                __nv_bfloat162 lo;
                __nv_bfloat162 hi2 = split_hi(v0, v1, lo);
                *(__nv_bfloat162*)&Ch[bb + n] = hi2;
                *(__nv_bfloat162*)&Cl[bb + n] = lo;
            }
        }
    }
}

// ---------------------------------------------------------------------------
// Output GEMM: ao-split x Wo (slab 3) -> fp32 row-major out
// ---------------------------------------------------------------------------
__global__ __launch_bounds__(256, 1)
void gemm_out(const __nv_bfloat16* __restrict__ Ahi,
              const __nv_bfloat16* __restrict__ Alo,
              float* __restrict__ C)
{
    const int col0 = blockIdx.x << 7;
    const int row0 = blockIdx.y * GTM;
    const __nv_bfloat16* Bhi = g_whi + 3 * WSLAB;
    const __nv_bfloat16* Blo = g_wlo + 3 * WSLAB;

    float acc[4][4][4];
#pragma unroll
    for (int i = 0; i < 4; i++)
#pragma unroll
        for (int j = 0; j < 4; j++)
#pragma unroll
            for (int q = 0; q < 4; q++) acc[i][j][q] = 0.f;

    gemm_mainloop(Ahi, Alo, Bhi, Blo, row0, col0, acc);

    const int lane = threadIdx.x & 31, wid = threadIdx.x >> 5;
    const int wm = wid & 1, wn = wid >> 1;
#pragma unroll
    for (int mf = 0; mf < 4; mf++) {
        int mrow = row0 + wm * 64 + mf * 16 + (lane >> 2);
        float* d0 = &C[(size_t)mrow * D_ + col0];
        float* d1 = d0 + (size_t)8 * D_;
#pragma unroll
        for (int nf = 0; nf < 4; nf++) {
            int n = wn * 32 + nf * 8 + (lane & 3) * 2;
            *(float2*)&d0[n] = make_float2(acc[mf][nf][0], acc[mf][nf][1]);
            *(float2*)&d1[n] = make_float2(acc[mf][nf][2], acc[mf][nf][3]);
        }
    }
}

// ---------------------------------------------------------------------------
// HMMA flash attention, causal. Br=128, Bc=64, 8 warps (16 rows each).
// S = 3-term bf16 split; P hi/lo split; PV = Ph*Vh + Pl*Vh + Ph*Vl.
// cp.async double buffer. Epilogue writes bf16 hi/lo split of output.
// ---------------------------------------------------------------------------
#define FBR 128
#define FBC 64
#define SQH 0
#define SQL 32768
#define SKV 65536                 // stages at 65536 + s*65536
#define FSMEMB (65536 + 2 * 65536)  // 192 KB

extern __shared__ char fsm8[];

__global__ __launch_bounds__(256, 1)
void flash_kernel()
{
    const uint32_t sb = smem_u32(fsm8);
    const int t = threadIdx.x, lane = t & 31, w = t >> 5;
    const int qt = (int)gridDim.x - 1 - (int)blockIdx.x;   // heavy tiles first
    const int bh = blockIdx.y;
    const int q0 = qt * FBR;
    const size_t hb = (size_t)bh * L_ * DH;

    // load Q hi/lo (once)
#pragma unroll
    for (int i = 0; i < 8; i++) {
        int u = t + i * 256;
        int c = u >> 10, r = (u >> 3) & 127, e8 = (u & 7) << 3;
        uint32_t so = c * 16384 + SWZ128((r << 7) + (e8 << 1));
        size_t go = hb + (size_t)(q0 + r) * DH + c * 64 + e8;
        *(uint4*)(fsm8 + SQH + so) = *(const uint4*)&g_qh[go];
        *(uint4*)(fsm8 + SQL + so) = *(const uint4*)&g_ql[go];
    }

#define LOADKV(j, s) do {                                                     \
    int kv0_ = (j) * FBC;                                                     \
    uint32_t stb = sb + SKV + (s) * 65536;                                    \
    _Pragma("unroll")                                                         \
    for (int i = 0; i < 4; i++) {                                             \
        int u = t + i * 256;                                                  \
        int c = u >> 9, r = (u >> 3) & 63, e8 = (u & 7) << 3;                 \
        uint32_t so = stb + c * 8192 + SWZ128((r << 7) + (e8 << 1));          \
        size_t go = hb + (size_t)(kv0_ + r) * DH + c * 64 + e8;               \
        CPASYNC16(so,         g_kh + go);                                     \
        CPASYNC16(so + 16384, g_kl + go);                                     \
        CPASYNC16(so + 32768, g_vh + go);                                     \
        CPASYNC16(so + 49152, g_vl + go);                                     \
    }                                                                         \
    CPCOMMIT();                                                               \
} while (0)

    const int jmax = qt * 2 + 1;
    LOADKV(0, 0);

    float o[16][4];
#pragma unroll
    for (int i = 0; i < 16; i++)
#pragma unroll
        for (int q = 0; q < 4; q++) o[i][q] = 0.f;
    float m0 = -INFINITY, m1 = -INFINITY, l0 = 0.f, l1 = 0.f;

    // per-lane invariant offsets
    const int mrow = w * 16 + ((lane >> 3) & 1) * 8 + (lane & 7);
    const int kAoff = (lane >> 4) << 4;
    const int nrow = ((lane >> 4) & 1) * 8 + (lane & 7);
    const int kBoff = ((lane >> 3) & 1) << 4;
    const int vrow = ((lane >> 3) & 1) * 8 + (lane & 7);
    const int vcol8 = ((lane >> 4) & 1) * 8;
    const int r0 = lane >> 2;          // warp-local row (also +8)
    const int cql = (lane & 3) * 2;    // col pair base within n8

    for (int j0 = 0; j0 <= jmax; j0++) {
        if (j0 < jmax) { LOADKV(j0 + 1, (j0 + 1) & 1); CPWAIT(1); }
        else CPWAIT(0);
        __syncthreads();

        const uint32_t kvb = sb + SKV + (j0 & 1) * 65536;
        const int kv0 = j0 * FBC;

        // ---- S = Q K^T (3-term) ----
        float s[8][4];
#pragma unroll
        for (int i = 0; i < 8; i++)
#pragma unroll
            for (int q = 0; q < 4; q++) s[i][q] = 0.f;

#pragma unroll
        for (int c = 0; c < 2; c++) {
#pragma unroll
            for (int kk = 0; kk < 4; kk++) {
                const int kb = kk * 32;
                uint32_t ah[4], al[4];
                uint32_t qa = sb + SQH + c * 16384 + SWZ128((mrow << 7) + kb + kAoff);
                LDSM4(ah, qa);
                LDSM4(al, qa + 32768);
#pragma unroll
                for (int ng = 0; ng < 4; ng++) {
                    uint32_t kh[4], kl[4];
                    uint32_t ka = kvb + c * 8192
                                + SWZ128(((ng * 16 + nrow) << 7) + kb + kBoff);
                    LDSM4(kh, ka);
                    LDSM4(kl, ka + 16384);
                    MMA16816(s[2*ng],   ah, kh[0], kh[1]);
                    MMA16816(s[2*ng+1], ah, kh[2], kh[3]);
                    MMA16816(s[2*ng],   ah, kl[0], kl[1]);
                    MMA16816(s[2*ng+1], ah, kl[2], kl[3]);
                    MMA16816(s[2*ng],   al, kh[0], kh[1]);
                    MMA16816(s[2*ng+1], al, kh[2], kh[3]);
                }
            }
        }

        // ---- causal mask ----
        const int qr0 = q0 + w * 16 + r0;
        if (kv0 + 63 > qr0) {
#pragma unroll
            for (int nf = 0; nf < 8; nf++) {
                int kc = kv0 + nf * 8 + cql;
                if (kc > qr0)     s[nf][0] = -INFINITY;
                if (kc + 1 > qr0) s[nf][1] = -INFINITY;
                if (kc > qr0 + 8)     s[nf][2] = -INFINITY;
                if (kc + 1 > qr0 + 8) s[nf][3] = -INFINITY;
            }
        }

        // ---- online softmax (rows warp-local; reduce over 4-lane row group) ----
        float mt0 = -INFINITY, mt1 = -INFINITY;
#pragma unroll
        for (int nf = 0; nf < 8; nf++) {
            mt0 = fmaxf(mt0, fmaxf(s[nf][0], s[nf][1]));
            mt1 = fmaxf(mt1, fmaxf(s[nf][2], s[nf][3]));
        }
        mt0 = fmaxf(mt0, __shfl_xor_sync(0xffffffffu, mt0, 1));
        mt0 = fmaxf(mt0, __shfl_xor_sync(0xffffffffu, mt0, 2));
        mt1 = fmaxf(mt1, __shfl_xor_sync(0xffffffffu, mt1, 1));
        mt1 = fmaxf(mt1, __shfl_xor_sync(0xffffffffu, mt1, 2));

        float nm0 = fmaxf(m0, mt0), nm1 = fmaxf(m1, mt1);
        float a0 = __expf(m0 - nm0), a1 = __expf(m1 - nm1);
        m0 = nm0; m1 = nm1;

        float rs0 = 0.f, rs1 = 0.f;
        uint32_t pah[4][4], pal[4][4];
#pragma unroll
        for (int kk = 0; kk < 4; kk++) {
#pragma unroll
            for (int half = 0; half < 2; half++) {
                int nf = 2 * kk + half;
                float p00 = __expf(s[nf][0] - m0);
                float p01 = __expf(s[nf][1] - m0);
                float p10 = __expf(s[nf][2] - m1);
                float p11 = __expf(s[nf][3] - m1);
                rs0 += p00 + p01;
                rs1 += p10 + p11;
                uint32_t ph0 = pack_bf16x2(p00, p01);
                uint32_t ph1 = pack_bf16x2(p10, p11);
                __nv_bfloat162 b0 = *(__nv_bfloat162*)&ph0;
                __nv_bfloat162 b1 = *(__nv_bfloat162*)&ph1;
                uint32_t pl0 = pack_bf16x2(p00 - __bfloat162float(b0.x),
                                           p01 - __bfloat162float(b0.y));
                uint32_t pl1 = pack_bf16x2(p10 - __bfloat162float(b1.x),
                                           p11 - __bfloat162float(b1.y));
                pah[kk][half * 2]     = ph0;
                pah[kk][half * 2 + 1] = ph1;
                pal[kk][half * 2]     = pl0;
                pal[kk][half * 2 + 1] = pl1;
            }
        }
        rs0 += __shfl_xor_sync(0xffffffffu, rs0, 1);
        rs0 += __shfl_xor_sync(0xffffffffu, rs0, 2);
        rs1 += __shfl_xor_sync(0xffffffffu, rs1, 1);
        rs1 += __shfl_xor_sync(0xffffffffu, rs1, 2);
        l0 = l0 * a0 + rs0;
        l1 = l1 * a1 + rs1;

#pragma unroll
        for (int nf = 0; nf < 16; nf++) {
            o[nf][0] *= a0; o[nf][1] *= a0;
            o[nf][2] *= a1; o[nf][3] *= a1;
        }

        // ---- O += Ph*(Vh+Vl) + Pl*Vh ----
#pragma unroll
        for (int kk = 0; kk < 4; kk++) {
#pragma unroll
            for (int dg = 0; dg < 8; dg++) {
                int dcol = dg * 16 + vcol8;
                int c = dcol >> 6, e = dcol & 63;
                uint32_t va = kvb + 32768 + c * 8192
                            + SWZ128(((kk * 16 + vrow) << 7) + (e << 1));
                uint32_t vh[4], vl[4];
                LDSM4T(vh, va);
                LDSM4T(vl, va + 16384);
                MMA16816(o[2*dg],   pah[kk], vh[0], vh[1]);
                MMA16816(o[2*dg+1], pah[kk], vh[2], vh[3]);
                MMA16816(o[2*dg],   pal[kk], vh[0], vh[1]);
                MMA16816(o[2*dg+1], pal[kk], vh[2], vh[3]);
                MMA16816(o[2*dg],   pah[kk], vl[0], vl[1]);
                MMA16816(o[2*dg+1], pah[kk], vl[2], vl[3]);
            }
        }
        __syncthreads();   // all warps done with this stage before it's refilled
    }

    // ---- epilogue: normalize, split to bf16 hi/lo, write [B,L,H*Dh] ----
    const int b = bh >> 4, h = bh & 15;
    const float inv0 = 1.f / l0, inv1 = 1.f / l1;
    const int qrow0 = q0 + w * 16 + r0;
    size_t o0b = ((size_t)b * L_ + qrow0) * D_ + h * DH;
    size_t o1b = o0b + (size_t)8 * D_;
#pragma unroll
    for (int nf = 0; nf < 16; nf++) {
        int col = nf * 8 + cql;
        __nv_bfloat162 lo0, lo1;
        __nv_bfloat162 hi0 = split_hi(o[nf][0] * inv0, o[nf][1] * inv0, lo0);
        __nv_bfloat162 hi1 = split_hi(o[nf][2] * inv1, o[nf][3] * inv1, lo1);
        *(__nv_bfloat162*)&g_xhi[o0b + col] = hi0;
        *(__nv_bfloat162*)&g_xlo[o0b + col] = lo0;
        *(__nv_bfloat162*)&g_xhi[o1b + col] = hi1;
        *(__nv_bfloat162*)&g_xlo[o1b + col] = lo1;
    }
}

// ---------------------------------------------------------------------------
extern "C" void kernel_launch(void* const* d_in, const int* in_sizes, int n_in,
                              void* d_out, int out_size)
{
    const float* x  = (const float*)d_in[0];
    const float* Wq = (const float*)d_in[1];
    const float* Wk = (const float*)d_in[2];
    const float* Wv = (const float*)d_in[3];
    const float* Wo = (const float*)d_in[4];
    float* out = (float*)d_out;

    __nv_bfloat16 *xh, *xl;
    cudaGetSymbolAddress((void**)&xh, g_xhi);
    cudaGetSymbolAddress((void**)&xl, g_xlo);

    cudaFuncSetAttribute(flash_kernel,
                         cudaFuncAttributeMaxDynamicSharedMemorySize, FSMEMB);
    cudaFuncSetAttribute(gemm_qkv,
                         cudaFuncAttributeMaxDynamicSharedMemorySize, GSMEM);
    cudaFuncSetAttribute(gemm_out,
                         cudaFuncAttributeMaxDynamicSharedMemorySize, GSMEM);

    const int n4 = M_ * KTOT / 4;
    dim3 tgrid(D_ / 32, KTOT / 32, 4), tblk(32, 8);

    freq_table<<<512, 256>>>();
    conv_plain<<<(n4 + 255) / 256, 256>>>(x, xh, xl, n4);
    conv_T4<<<tgrid, tblk>>>(Wq, Wk, Wv, Wo);

    gemm_qkv<<<dim3(48, 32), 256, GSMEM>>>(xh, xl);

    flash_kernel<<<dim3(16, 32), 256, FSMEMB>>>();   // overwrites xh/xl with ao split

    gemm_out<<<dim3(16, 32), 256, GSMEM>>>(xh, xl, out);
}